// round 3
// baseline (speedup 1.0000x reference)
#include <cuda_runtime.h>
#include <cuda_bf16.h>

#define N_NODES 100000
#define MAX_E   1600000

// ---------------- scratch (static device globals; no allocation) ------------
__device__ __align__(16) float g_deg[N_NODES];        // in-degree (float)
__device__ __align__(16) float g_agg1[N_NODES * 64];  // layer-1 neighbor sum
__device__ __align__(16) float g_p[N_NODES * 32];     // h @ W2l^T (layer-2 messages)
__device__ __align__(16) float g_agg2[N_NODES * 32];  // layer-2 neighbor sum
__device__ __align__(16) int2  g_edges[MAX_E];        // packed (src, dst)

// ---------------- K0: zero scratch ------------------------------------------
__global__ __launch_bounds__(256) void zero_kernel()
{
    const int n_deg  = N_NODES / 4;            // 25000 float4
    const int n_a1   = N_NODES * 16;           // 1.6M float4
    const int n_a2   = N_NODES * 8;            // 0.8M float4
    const int total  = n_deg + n_a1 + n_a2;
    float4 z = make_float4(0.f, 0.f, 0.f, 0.f);
    for (int t = blockIdx.x * blockDim.x + threadIdx.x; t < total;
         t += gridDim.x * blockDim.x) {
        if (t < n_deg) {
            reinterpret_cast<float4*>(g_deg)[t] = z;
        } else if (t < n_deg + n_a1) {
            reinterpret_cast<float4*>(g_agg1)[t - n_deg] = z;
        } else {
            reinterpret_cast<float4*>(g_agg2)[t - n_deg - n_a1] = z;
        }
    }
}

// ---------------- K1: pack int32 edges -> int2, accumulate degree -----------
// NOTE: edge_index is int32 on device (JAX default x64-disabled downcasts int64)
__global__ __launch_bounds__(256) void pack_edges_kernel(
    const int* __restrict__ ei1, const int* __restrict__ ei2,
    int E1, int E2)
{
    int t = blockIdx.x * blockDim.x + threadIdx.x;
    int E = E1 + E2;
    if (t >= E) return;
    int s, d;
    if (t < E1) { s = ei1[t];      d = ei1[t + E1]; }
    else        { int u = t - E1;  s = ei2[u];  d = ei2[u + E2]; }
    g_edges[t] = make_int2(s, d);
    atomicAdd(&g_deg[d], 1.0f);
}

// ---------------- K2: scatter layer 1 (64 floats/edge) ----------------------
// thread per (edge, 4-float chunk): float4 load, 4 scalar atomicAdds
__global__ __launch_bounds__(256) void scatter64_kernel(
    const float4* __restrict__ x4, int total)   // total = E*16
{
    int t = blockIdx.x * blockDim.x + threadIdx.x;
    if (t >= total) return;
    int e = t >> 4, c = t & 15;
    int2 ed = g_edges[e];
    float4 v = x4[ed.x * 16 + c];
    float* dst = &g_agg1[ed.y * 64 + c * 4];
    atomicAdd(dst + 0, v.x);
    atomicAdd(dst + 1, v.y);
    atomicAdd(dst + 2, v.z);
    atomicAdd(dst + 3, v.w);
}

// ---------------- K3: combine layer 1 + project for layer 2 -----------------
// warp-per-node:
//   h    = relu( (agg1/deg) @ W1l^T + b1 + x @ W1r^T )   (registers only)
//   g_p  = h @ W2l^T
//   out  = h @ W2r^T + b2          (layer-2 self term)
__global__ __launch_bounds__(256) void combine1_kernel(
    const float* __restrict__ x,
    const float* __restrict__ W1l, const float* __restrict__ b1,
    const float* __restrict__ W1r,
    const float* __restrict__ W2l, const float* __restrict__ b2,
    const float* __restrict__ W2r,
    float* __restrict__ out)
{
    // transposed weights in shared: s[k*cols + j] = W[j*64 + k]
    __shared__ float sW1l[64 * 64];
    __shared__ float sW1r[64 * 64];
    __shared__ float sW2l[64 * 32];
    __shared__ float sW2r[64 * 32];

    int tid = threadIdx.x;
    for (int i = tid; i < 4096; i += blockDim.x) {
        int j = i & 63, k = i >> 6;
        sW1l[i] = W1l[j * 64 + k];
        sW1r[i] = W1r[j * 64 + k];
    }
    for (int i = tid; i < 2048; i += blockDim.x) {
        int c = i & 31, k = i >> 5;
        sW2l[i] = W2l[c * 64 + k];
        sW2r[i] = W2r[c * 64 + k];
    }
    __syncthreads();

    int warp = tid >> 5, lane = tid & 31;
    int node = blockIdx.x * 8 + warp;
    if (node >= N_NODES) return;

    float dinv = 1.0f / fmaxf(g_deg[node], 1.0f);
    float m0 = g_agg1[node * 64 + lane]      * dinv;
    float m1 = g_agg1[node * 64 + 32 + lane] * dinv;
    float x0 = x[node * 64 + lane];
    float x1 = x[node * 64 + 32 + lane];

    float a0 = 0.f, a1 = 0.f;
    #pragma unroll
    for (int k = 0; k < 32; k++) {
        float bm = __shfl_sync(0xffffffffu, m0, k);
        float bx = __shfl_sync(0xffffffffu, x0, k);
        a0 = fmaf(bm, sW1l[k * 64 + lane],      a0);
        a0 = fmaf(bx, sW1r[k * 64 + lane],      a0);
        a1 = fmaf(bm, sW1l[k * 64 + 32 + lane], a1);
        a1 = fmaf(bx, sW1r[k * 64 + 32 + lane], a1);
    }
    #pragma unroll
    for (int k = 0; k < 32; k++) {
        float bm = __shfl_sync(0xffffffffu, m1, k);
        float bx = __shfl_sync(0xffffffffu, x1, k);
        a0 = fmaf(bm, sW1l[(k + 32) * 64 + lane],      a0);
        a0 = fmaf(bx, sW1r[(k + 32) * 64 + lane],      a0);
        a1 = fmaf(bm, sW1l[(k + 32) * 64 + 32 + lane], a1);
        a1 = fmaf(bx, sW1r[(k + 32) * 64 + 32 + lane], a1);
    }
    float h0 = fmaxf(a0 + __ldg(&b1[lane]),      0.0f);
    float h1 = fmaxf(a1 + __ldg(&b1[lane + 32]), 0.0f);

    // p[c] = sum_k h[k] * W2l[c][k];  q[c] = sum_k h[k] * W2r[c][k]
    float pacc = 0.f, qacc = 0.f;
    #pragma unroll
    for (int k = 0; k < 32; k++) {
        float bh = __shfl_sync(0xffffffffu, h0, k);
        pacc = fmaf(bh, sW2l[k * 32 + lane], pacc);
        qacc = fmaf(bh, sW2r[k * 32 + lane], qacc);
    }
    #pragma unroll
    for (int k = 0; k < 32; k++) {
        float bh = __shfl_sync(0xffffffffu, h1, k);
        pacc = fmaf(bh, sW2l[(k + 32) * 32 + lane], pacc);
        qacc = fmaf(bh, sW2r[(k + 32) * 32 + lane], qacc);
    }
    g_p[node * 32 + lane] = pacc;
    out[node * 32 + lane] = qacc + __ldg(&b2[lane]);
}

// ---------------- K4: scatter layer 2 (32 floats/edge) ----------------------
__global__ __launch_bounds__(256) void scatter32_kernel(int total)  // total = E*8
{
    int t = blockIdx.x * blockDim.x + threadIdx.x;
    if (t >= total) return;
    int e = t >> 3, c = t & 7;
    int2 ed = g_edges[e];
    const float4* p4 = reinterpret_cast<const float4*>(g_p);
    float4 v = p4[ed.x * 8 + c];
    float* dst = &g_agg2[ed.y * 32 + c * 4];
    atomicAdd(dst + 0, v.x);
    atomicAdd(dst + 1, v.y);
    atomicAdd(dst + 2, v.z);
    atomicAdd(dst + 3, v.w);
}

// ---------------- K5: finalize: out += agg2 / max(deg,1) --------------------
__global__ __launch_bounds__(256) void finalize_kernel(float* __restrict__ out, int n)
{
    int t = blockIdx.x * blockDim.x + threadIdx.x;
    if (t >= n) return;
    int node = t >> 5;
    out[t] += g_agg2[t] * (1.0f / fmaxf(g_deg[node], 1.0f));
}

// ---------------- launch -----------------------------------------------------
extern "C" void kernel_launch(void* const* d_in, const int* in_sizes, int n_in,
                              void* d_out, int out_size)
{
    const float* x    = (const float*)d_in[0];
    const int*   ei1  = (const int*)d_in[1];     // int32 (JAX x64 disabled)
    const int*   ei2  = (const int*)d_in[3];
    const float* W1l  = (const float*)d_in[5];
    const float* b1   = (const float*)d_in[6];
    const float* W1r  = (const float*)d_in[7];
    const float* W2l  = (const float*)d_in[8];
    const float* b2   = (const float*)d_in[9];
    const float* W2r  = (const float*)d_in[10];
    float*       out  = (float*)d_out;

    int E1 = in_sizes[1] / 2;
    int E2 = in_sizes[3] / 2;
    int E  = E1 + E2;

    // K0: zero scratch
    zero_kernel<<<2048, 256>>>();

    // K1: pack + degree
    pack_edges_kernel<<<(E + 255) / 256, 256>>>(ei1, ei2, E1, E2);

    // K2: scatter x into agg1
    int total1 = E * 16;
    scatter64_kernel<<<(total1 + 255) / 256, 256>>>(
        reinterpret_cast<const float4*>(x), total1);

    // K3: combine layer 1, project layer-2 messages + self term
    combine1_kernel<<<(N_NODES + 7) / 8, 256>>>(x, W1l, b1, W1r, W2l, b2, W2r, out);

    // K4: scatter p into agg2
    int total2 = E * 8;
    scatter32_kernel<<<(total2 + 255) / 256, 256>>>(total2);

    // K5: finalize
    int n_out = N_NODES * 32;
    finalize_kernel<<<(n_out + 255) / 256, 256>>>(out, n_out);
}